// round 16
// baseline (speedup 1.0000x reference)
#include <cuda_runtime.h>
#include <cstdint>

// GraphSAGE via CSR, with root-branch overlap on a forked stream:
//   pre (legacy):   memset(deg); k_deg; k_scan(+W transpose); k_build
//   s2 (forked):    k_root_l : r = x_l @ Wr^T + b     (FMA-bound)
//   legacy:         k_gather_l (L2-bound)  ... overlaps k_root_l
//                   k_fin_l : x_{l+1} = relu(agg @ Wl^T + r)

#define NODES_MAX 100000
#define EDGES_MAX 1600000
#define DD 64
#define WTP 68            // transposed weight stride (mult of 4 -> LDS.128 ok)
#define NPAD 68           // input tile stride
#define WT_MAT (64*WTP)   // 4352 floats per matrix
#define HALF_SMEM ((WT_MAT + 128*NPAD) * 4)   // 52224 bytes (root/fin)

__device__ float g_agg [(size_t)NODES_MAX * DD];
__device__ float g_r   [(size_t)NODES_MAX * DD];
__device__ float g_bufA[(size_t)NODES_MAX * DD];
__device__ float g_bufB[(size_t)NODES_MAX * DD];
__device__ float g_wT  [8 * 2 * WT_MAT];          // [l][mat][k][j], stride WTP
__device__ float g_inv [NODES_MAX];
__device__ int   g_deg [NODES_MAX];
__device__ int   g_row [NODES_MAX];
__device__ int   g_cur [NODES_MAX];
__device__ int   g_col [EDGES_MAX];
__device__ unsigned long long g_state[512];       // lookback: (flag<<32)|sum

#define FLG_AGG 1ULL
#define FLG_INC 2ULL

// ---------------------------------------------------------------------------
__device__ __forceinline__ int probe_is64(const int* __restrict__ ei32) {
    int o = ei32[1] | ei32[3] | ei32[5] | ei32[7]
          | ei32[9] | ei32[11] | ei32[13] | ei32[15];
    return o == 0;
}

#define FFMA2(d, a, b) \
    asm("fma.rn.f32x2 %0, %1, %2, %0;" : "+l"(d) : "l"(a), "l"(b))
#define PACK2(d, lo, hi) \
    asm("mov.b64 %0, {%1, %2};" : "=l"(d) : "f"(lo), "f"(hi))
#define UNPACK2(lo, hi, s) \
    asm("mov.b64 {%0, %1}, %2;" : "=f"(lo), "=f"(hi) : "l"(s))

// ---------------------------------------------------------------------------
__global__ void __launch_bounds__(256) k_deg(const void* __restrict__ ei, int E) {
    if (blockIdx.x == 0) {
        g_state[threadIdx.x]       = 0ull;
        g_state[threadIdx.x + 256] = 0ull;
    }
    int t = blockIdx.x * blockDim.x + threadIdx.x;
    int e0 = t * 2;
    if (e0 >= E) return;
    int is64 = probe_is64((const int*)ei);
    int d0, d1;
    if (is64) {
        longlong2 p = ((const longlong2*)ei)[(E + e0) >> 1];
        d0 = (int)p.x; d1 = (int)p.y;
    } else {
        int2 p = ((const int2*)ei)[(E + e0) >> 1];
        d0 = p.x; d1 = p.y;
    }
    atomicAdd(&g_deg[d0], 1);
    if (e0 + 1 < E) atomicAdd(&g_deg[d1], 1);
}

// ---------------------------------------------------------------------------
__global__ void __launch_bounds__(256)
k_scan(int n, int nb,
       const float* __restrict__ Wl, const float* __restrict__ Wr, int L)
{
    if ((int)blockIdx.x >= nb) {                  // weight transpose duty
        int idx = ((int)blockIdx.x - nb) * 256 + threadIdx.x;
        int tot = L * 2 * 4096;
        if (idx < tot) {
            int l  = idx >> 13;
            int r  = idx & 8191;
            int m  = r >> 12;
            int jk = r & 4095;
            int j  = jk >> 6;
            int k  = jk & 63;
            const float* W = m ? Wr : Wl;
            g_wT[(size_t)(l * 2 + m) * WT_MAT + k * WTP + j] =
                W[(size_t)l * 4096 + j * 64 + k];
        }
        return;
    }

    __shared__ int s[256];
    __shared__ int s_prefix;
    const int tid = threadIdx.x;
    const int b   = blockIdx.x;
    const int v   = b * 256 + tid;
    int d = (v < n) ? g_deg[v] : 0;

    s[tid] = d;
    __syncthreads();
    #pragma unroll
    for (int off = 1; off < 256; off <<= 1) {
        int t = (tid >= off) ? s[tid - off] : 0;
        __syncthreads();
        s[tid] += t;
        __syncthreads();
    }
    int total = s[255];

    if (tid == 0) {
        unsigned long long st = ((b == 0 ? FLG_INC : FLG_AGG) << 32) | (unsigned)total;
        atomicExch(&g_state[b], st);
        if (b == 0) s_prefix = 0;
    }

    if (b > 0 && tid < 32) {
        const int lane = tid;
        unsigned prefix = 0;
        int idx = b - 1;
        while (true) {
            int look = idx - lane;
            unsigned long long st = (look >= 0) ? atomicAdd(&g_state[look], 0ULL)
                                                : (FLG_INC << 32);
            unsigned flag = (unsigned)(st >> 32);
            unsigned val  = (unsigned)st;
            unsigned bEmpty = __ballot_sync(0xffffffffu, flag == 0u);
            unsigned bInc   = __ballot_sync(0xffffffffu, flag == (unsigned)FLG_INC);
            int firstInc   = bInc   ? (__ffs(bInc) - 1)   : 32;
            int firstEmpty = bEmpty ? (__ffs(bEmpty) - 1) : 32;
            if (firstEmpty < firstInc) continue;
            int lim = firstInc < 31 ? firstInc : 31;
            unsigned c = (lane <= lim) ? val : 0;
            #pragma unroll
            for (int o = 16; o > 0; o >>= 1) c += __shfl_down_sync(0xffffffffu, c, o);
            c = __shfl_sync(0xffffffffu, c, 0);
            prefix += c;
            if (firstInc < 32) break;
            idx -= 32;
        }
        if (lane == 0) {
            atomicExch(&g_state[b], (FLG_INC << 32) | (unsigned)(prefix + total));
            s_prefix = (int)prefix;
        }
    }
    __syncthreads();

    if (v < n) {
        int r = s_prefix + s[tid] - d;
        g_row[v] = r;
        g_cur[v] = r;
        g_inv[v] = 1.0f / (float)max(d, 1);
    }
}

// ---------------------------------------------------------------------------
__global__ void __launch_bounds__(256) k_build(const void* __restrict__ ei, int E) {
    int t = blockIdx.x * blockDim.x + threadIdx.x;
    int e0 = t * 2;
    if (e0 >= E) return;
    int is64 = probe_is64((const int*)ei);
    int s0, s1, d0, d1;
    if (is64) {
        longlong2 sp = ((const longlong2*)ei)[e0 >> 1];
        longlong2 dp = ((const longlong2*)ei)[(E + e0) >> 1];
        s0 = (int)sp.x; s1 = (int)sp.y;
        d0 = (int)dp.x; d1 = (int)dp.y;
    } else {
        int2 sp = ((const int2*)ei)[e0 >> 1];
        int2 dp = ((const int2*)ei)[(E + e0) >> 1];
        s0 = sp.x; s1 = sp.y;
        d0 = dp.x; d1 = dp.y;
    }
    int p0 = atomicAdd(&g_cur[d0], 1);
    g_col[p0] = s0;
    if (e0 + 1 < E) {
        int p1 = atomicAdd(&g_cur[d1], 1);
        g_col[p1] = s1;
    }
}

// ---------------------------------------------------------------------------
// Gather (R13 form): warp per node, lane owns cols [2*lane, 2*lane+1].
__global__ void __launch_bounds__(256)
k_gather(const float* __restrict__ xin, int n)
{
    int gw   = (blockIdx.x * blockDim.x + threadIdx.x) >> 5;
    int lane = threadIdx.x & 31;
    if (gw >= n) return;
    const int v = gw;

    const float2* x2 = (const float2*)xin;
    float2 acc = make_float2(0.f, 0.f);

    int rs  = g_row[v];
    int end = rs + g_deg[v];
    int e = rs;
    for (; e + 8 <= end; e += 8) {
        int s0 = g_col[e+0], s1 = g_col[e+1], s2 = g_col[e+2], s3 = g_col[e+3];
        int s4 = g_col[e+4], s5 = g_col[e+5], s6 = g_col[e+6], s7 = g_col[e+7];
        float2 a0 = x2[(size_t)s0*32 + lane], a1 = x2[(size_t)s1*32 + lane];
        float2 a2 = x2[(size_t)s2*32 + lane], a3 = x2[(size_t)s3*32 + lane];
        float2 a4 = x2[(size_t)s4*32 + lane], a5 = x2[(size_t)s5*32 + lane];
        float2 a6 = x2[(size_t)s6*32 + lane], a7 = x2[(size_t)s7*32 + lane];
        acc.x += ((a0.x + a1.x) + (a2.x + a3.x)) + ((a4.x + a5.x) + (a6.x + a7.x));
        acc.y += ((a0.y + a1.y) + (a2.y + a3.y)) + ((a4.y + a5.y) + (a6.y + a7.y));
    }
    for (; e + 4 <= end; e += 4) {
        int s0 = g_col[e+0], s1 = g_col[e+1], s2 = g_col[e+2], s3 = g_col[e+3];
        float2 a0 = x2[(size_t)s0*32 + lane], a1 = x2[(size_t)s1*32 + lane];
        float2 a2 = x2[(size_t)s2*32 + lane], a3 = x2[(size_t)s3*32 + lane];
        acc.x += (a0.x + a1.x) + (a2.x + a3.x);
        acc.y += (a0.y + a1.y) + (a2.y + a3.y);
    }
    for (; e < end; ++e) {
        float2 a0 = x2[(size_t)g_col[e]*32 + lane];
        acc.x += a0.x; acc.y += a0.y;
    }
    float iv = g_inv[v];
    acc.x *= iv; acc.y *= iv;
    *(float2*)(g_agg + (size_t)v * 64 + lane * 2) = acc;
}

// ---------------------------------------------------------------------------
// Root GEMM: r = x @ Wr^T + b.   128 nodes / 128 threads; 8 nodes x 8 feats.
__global__ void __launch_bounds__(128, 4)
k_root(const float* __restrict__ xin, const float* __restrict__ bl,
       int n, int l)
{
    extern __shared__ float smem[];
    float* sW = smem;                  // [k][j], stride WTP
    float* sX = sW + WT_MAT;           // [node][k], stride NPAD

    const int tid  = threadIdx.x;
    const int base = blockIdx.x * 128;

    {
        const float4* wsrc = (const float4*)(g_wT + ((size_t)l * 2 + 1) * WT_MAT);
        float4* wdst = (float4*)sW;
        #pragma unroll 1
        for (int idx = tid; idx < WT_MAT / 4; idx += 128)
            wdst[idx] = wsrc[idx];
    }
    for (int idx = tid; idx < 128 * 16; idx += 128) {
        int v = idx >> 4, c = idx & 15;
        int vg = base + v;
        float4 xv = make_float4(0.f, 0.f, 0.f, 0.f);
        if (vg < n) xv = *(const float4*)(xin + (size_t)vg * 64 + c * 4);
        *(float4*)(sX + v * NPAD + c * 4) = xv;
    }
    __syncthreads();

    const int ng = tid & 15;
    const int jg = tid >> 4;
    const int j0 = jg * 8;

    unsigned long long acc2[8][4];
    #pragma unroll
    for (int i = 0; i < 8; ++i)
        #pragma unroll
        for (int p = 0; p < 4; ++p) acc2[i][p] = 0ull;

    #pragma unroll 1
    for (int k2 = 0; k2 < 32; ++k2) {
        int k0 = k2 * 2;
        ulonglong2 w0a = *(const ulonglong2*)(sW + (k0+0) * WTP + j0);
        ulonglong2 w0b = *(const ulonglong2*)(sW + (k0+0) * WTP + j0 + 4);
        ulonglong2 w1a = *(const ulonglong2*)(sW + (k0+1) * WTP + j0);
        ulonglong2 w1b = *(const ulonglong2*)(sW + (k0+1) * WTP + j0 + 4);
        #pragma unroll
        for (int i = 0; i < 8; ++i) {
            int v = i * 16 + ng;
            float2 xv = *(const float2*)(sX + v * NPAD + k0);
            unsigned long long b;
            PACK2(b, xv.x, xv.x);
            FFMA2(acc2[i][0], w0a.x, b); FFMA2(acc2[i][1], w0a.y, b);
            FFMA2(acc2[i][2], w0b.x, b); FFMA2(acc2[i][3], w0b.y, b);
            PACK2(b, xv.y, xv.y);
            FFMA2(acc2[i][0], w1a.x, b); FFMA2(acc2[i][1], w1a.y, b);
            FFMA2(acc2[i][2], w1b.x, b); FFMA2(acc2[i][3], w1b.y, b);
        }
    }

    float4 bias0 = *(const float4*)(bl + j0);
    float4 bias1 = *(const float4*)(bl + j0 + 4);

    #pragma unroll
    for (int i = 0; i < 8; ++i) {
        int vg = base + i * 16 + ng;
        if (vg < n) {
            float4 o0, o1;
            float lo, hi;
            UNPACK2(lo, hi, acc2[i][0]); o0.x = lo; o0.y = hi;
            UNPACK2(lo, hi, acc2[i][1]); o0.z = lo; o0.w = hi;
            UNPACK2(lo, hi, acc2[i][2]); o1.x = lo; o1.y = hi;
            UNPACK2(lo, hi, acc2[i][3]); o1.z = lo; o1.w = hi;
            o0.x += bias0.x; o0.y += bias0.y; o0.z += bias0.z; o0.w += bias0.w;
            o1.x += bias1.x; o1.y += bias1.y; o1.z += bias1.z; o1.w += bias1.w;
            *(float4*)(g_r + (size_t)vg * 64 + j0)     = o0;
            *(float4*)(g_r + (size_t)vg * 64 + j0 + 4) = o1;
        }
    }
}

// ---------------------------------------------------------------------------
// Final GEMM: out = relu(agg @ Wl^T + r).
__global__ void __launch_bounds__(128, 4)
k_fin(float* __restrict__ xout, int n, int l)
{
    extern __shared__ float smem[];
    float* sW = smem;                  // [k][j], stride WTP
    float* sA = sW + WT_MAT;           // [node][k], stride NPAD

    const int tid  = threadIdx.x;
    const int base = blockIdx.x * 128;

    {
        const float4* wsrc = (const float4*)(g_wT + ((size_t)l * 2 + 0) * WT_MAT);
        float4* wdst = (float4*)sW;
        #pragma unroll 1
        for (int idx = tid; idx < WT_MAT / 4; idx += 128)
            wdst[idx] = wsrc[idx];
    }
    for (int idx = tid; idx < 128 * 16; idx += 128) {
        int v = idx >> 4, c = idx & 15;
        int vg = base + v;
        float4 a = make_float4(0.f, 0.f, 0.f, 0.f);
        if (vg < n) a = *(const float4*)(g_agg + (size_t)vg * 64 + c * 4);
        *(float4*)(sA + v * NPAD + c * 4) = a;
    }
    __syncthreads();

    const int ng = tid & 15;
    const int jg = tid >> 4;
    const int j0 = jg * 8;

    unsigned long long acc2[8][4];
    #pragma unroll
    for (int i = 0; i < 8; ++i)
        #pragma unroll
        for (int p = 0; p < 4; ++p) acc2[i][p] = 0ull;

    #pragma unroll 1
    for (int k2 = 0; k2 < 32; ++k2) {
        int k0 = k2 * 2;
        ulonglong2 w0a = *(const ulonglong2*)(sW + (k0+0) * WTP + j0);
        ulonglong2 w0b = *(const ulonglong2*)(sW + (k0+0) * WTP + j0 + 4);
        ulonglong2 w1a = *(const ulonglong2*)(sW + (k0+1) * WTP + j0);
        ulonglong2 w1b = *(const ulonglong2*)(sW + (k0+1) * WTP + j0 + 4);
        #pragma unroll
        for (int i = 0; i < 8; ++i) {
            int v = i * 16 + ng;
            float2 a = *(const float2*)(sA + v * NPAD + k0);
            unsigned long long b;
            PACK2(b, a.x, a.x);
            FFMA2(acc2[i][0], w0a.x, b); FFMA2(acc2[i][1], w0a.y, b);
            FFMA2(acc2[i][2], w0b.x, b); FFMA2(acc2[i][3], w0b.y, b);
            PACK2(b, a.y, a.y);
            FFMA2(acc2[i][0], w1a.x, b); FFMA2(acc2[i][1], w1a.y, b);
            FFMA2(acc2[i][2], w1b.x, b); FFMA2(acc2[i][3], w1b.y, b);
        }
    }

    #pragma unroll
    for (int i = 0; i < 8; ++i) {
        int vg = base + i * 16 + ng;
        if (vg < n) {
            float4 r0 = *(const float4*)(g_r + (size_t)vg * 64 + j0);
            float4 r1 = *(const float4*)(g_r + (size_t)vg * 64 + j0 + 4);
            float4 o0, o1;
            float lo, hi;
            UNPACK2(lo, hi, acc2[i][0]); o0.x = lo; o0.y = hi;
            UNPACK2(lo, hi, acc2[i][1]); o0.z = lo; o0.w = hi;
            UNPACK2(lo, hi, acc2[i][2]); o1.x = lo; o1.y = hi;
            UNPACK2(lo, hi, acc2[i][3]); o1.z = lo; o1.w = hi;
            o0.x = fmaxf(o0.x + r0.x, 0.f);
            o0.y = fmaxf(o0.y + r0.y, 0.f);
            o0.z = fmaxf(o0.z + r0.z, 0.f);
            o0.w = fmaxf(o0.w + r0.w, 0.f);
            o1.x = fmaxf(o1.x + r1.x, 0.f);
            o1.y = fmaxf(o1.y + r1.y, 0.f);
            o1.z = fmaxf(o1.z + r1.z, 0.f);
            o1.w = fmaxf(o1.w + r1.w, 0.f);
            *(float4*)(xout + (size_t)vg * 64 + j0)     = o0;
            *(float4*)(xout + (size_t)vg * 64 + j0 + 4) = o1;
        }
    }
}

// ---------------------------------------------------------------------------
extern "C" void kernel_launch(void* const* d_in, const int* in_sizes, int n_in,
                              void* d_out, int out_size)
{
    const float* x  = (const float*)d_in[0];
    const float* Wl = (const float*)d_in[1];
    const float* bl = (const float*)d_in[2];
    const float* Wr = (const float*)d_in[3];
    const void*  ei = d_in[4];

    const int n = in_sizes[0] / DD;
    const int E = in_sizes[4] / 2;
    const int L = in_sizes[1] / (DD * DD);

    float *bufA = nullptr, *bufB = nullptr;
    void* degp = nullptr;
    cudaGetSymbolAddress((void**)&bufA, g_bufA);
    cudaGetSymbolAddress((void**)&bufB, g_bufB);
    cudaGetSymbolAddress(&degp, g_deg);

    cudaFuncSetAttribute(k_root, cudaFuncAttributeMaxDynamicSharedMemorySize,
                         HALF_SMEM);
    cudaFuncSetAttribute(k_fin, cudaFuncAttributeMaxDynamicSharedMemorySize,
                         HALF_SMEM);

    const int nb  = (n + 255) / 256;
    const int wb  = (L * 2 * 4096 + 255) / 256;
    const int eb2 = (E / 2 + 255) / 256;
    const int gb  = (n * 32 + 255) / 256;
    const int mb  = (n + 127) / 128;

    // Forked stream for root-branch GEMMs (graph-capture-safe fork/join).
    cudaStream_t s2;
    cudaStreamCreateWithFlags(&s2, cudaStreamNonBlocking);
    cudaEvent_t evFork, evR0, evR1, evR2, evF0, evF1;
    cudaEventCreateWithFlags(&evFork, cudaEventDisableTiming);
    cudaEventCreateWithFlags(&evR0, cudaEventDisableTiming);
    cudaEventCreateWithFlags(&evR1, cudaEventDisableTiming);
    cudaEventCreateWithFlags(&evR2, cudaEventDisableTiming);
    cudaEventCreateWithFlags(&evF0, cudaEventDisableTiming);
    cudaEventCreateWithFlags(&evF1, cudaEventDisableTiming);

    cudaEventRecord(evFork, 0);
    cudaStreamWaitEvent(s2, evFork, 0);

    cudaMemsetAsync(degp, 0, (size_t)n * sizeof(int));
    k_deg<<<eb2, 256>>>(ei, E);                               // launch 0
    k_scan<<<nb + wb, 256>>>(n, nb, Wl, Wr, L);               // launch 1
    k_build<<<eb2, 256>>>(ei, E);                             // launch 2

    const float* cur = x;
    float* outs[3];
    for (int l = 0; l < L; ++l)
        outs[l] = (l == L - 1) ? (float*)d_out : ((l & 1) ? bufB : bufA);

    // layer 0: root on s2 overlaps preprocessing (issued 4th -> ncu target)
    k_root<<<mb, 128, HALF_SMEM, s2>>>(cur, bl, n, 0);        // launch 3
    cudaEventRecord(evR0, s2);

    k_gather<<<gb, 256>>>(cur, n);                            // launch 4
    cudaStreamWaitEvent(0, evR0, 0);
    k_fin<<<mb, 128, HALF_SMEM>>>(outs[0], n, 0);             // launch 5
    cudaEventRecord(evF0, 0);
    cur = outs[0];

    if (L > 1) {
        cudaStreamWaitEvent(s2, evF0, 0);
        k_root<<<mb, 128, HALF_SMEM, s2>>>(cur, bl + DD, n, 1);
        cudaEventRecord(evR1, s2);

        k_gather<<<gb, 256>>>(cur, n);                        // overlaps root1
        cudaStreamWaitEvent(0, evR1, 0);
        k_fin<<<mb, 128, HALF_SMEM>>>(outs[1], n, 1);
        cudaEventRecord(evF1, 0);
        cur = outs[1];
    }
    if (L > 2) {
        cudaStreamWaitEvent(s2, evF1, 0);
        k_root<<<mb, 128, HALF_SMEM, s2>>>(cur, bl + 2 * DD, n, 2);
        cudaEventRecord(evR2, s2);

        k_gather<<<gb, 256>>>(cur, n);                        // overlaps root2
        cudaStreamWaitEvent(0, evR2, 0);
        k_fin<<<mb, 128, HALF_SMEM>>>(outs[2], n, 2);
    }
}

// round 17
// speedup vs baseline: 1.2210x; 1.2210x over previous
#include <cuda_runtime.h>
#include <cstdint>

// GraphSAGE via CSR:
//   pre:   memset(deg); k_deg; k_scan (lookback + weight transpose); k_build
//   layer: k_gather (warp-per-node mean, LTS-cap-bound)
//          k_gemm   (256 thr, 4 nodes x 8 feats / thread, FFMA2,
//                    broadcast weight LDS, conflict-free NPAD=66)

#define NODES_MAX 100000
#define EDGES_MAX 1600000
#define DD 64
#define WTP 68            // transposed weight stride (mult of 4 -> LDS.128 ok)
#define NPAD 66           // input tile stride: lane stride ≡ bank 2 -> conflict-free
#define WT_MAT (64*WTP)   // 4352 floats per matrix
#define GEMM_SMEM ((2*WT_MAT + 2*128*NPAD) * 4)   // 102400 bytes

__device__ float g_agg [(size_t)NODES_MAX * DD];
__device__ float g_bufA[(size_t)NODES_MAX * DD];
__device__ float g_bufB[(size_t)NODES_MAX * DD];
__device__ float g_wT  [8 * 2 * WT_MAT];          // [l][mat][k][j], stride WTP
__device__ float g_inv [NODES_MAX];
__device__ int   g_deg [NODES_MAX];
__device__ int   g_row [NODES_MAX];
__device__ int   g_cur [NODES_MAX];
__device__ int   g_col [EDGES_MAX];
__device__ unsigned long long g_state[512];       // lookback: (flag<<32)|sum

#define FLG_AGG 1ULL
#define FLG_INC 2ULL

// ---------------------------------------------------------------------------
__device__ __forceinline__ int probe_is64(const int* __restrict__ ei32) {
    int o = ei32[1] | ei32[3] | ei32[5] | ei32[7]
          | ei32[9] | ei32[11] | ei32[13] | ei32[15];
    return o == 0;
}

#define FFMA2(d, a, b) \
    asm("fma.rn.f32x2 %0, %1, %2, %0;" : "+l"(d) : "l"(a), "l"(b))
#define PACK2(d, lo, hi) \
    asm("mov.b64 %0, {%1, %2};" : "=l"(d) : "f"(lo), "f"(hi))
#define UNPACK2(lo, hi, s) \
    asm("mov.b64 {%0, %1}, %2;" : "=f"(lo), "=f"(hi) : "l"(s))

// ---------------------------------------------------------------------------
// launch 0: degree count, 2 edges/thread; block 0 also clears lookback state.
__global__ void __launch_bounds__(256) k_deg(const void* __restrict__ ei, int E) {
    if (blockIdx.x == 0) {
        g_state[threadIdx.x]       = 0ull;
        g_state[threadIdx.x + 256] = 0ull;
    }
    int t = blockIdx.x * blockDim.x + threadIdx.x;
    int e0 = t * 2;
    if (e0 >= E) return;
    int is64 = probe_is64((const int*)ei);
    int d0, d1;
    if (is64) {
        longlong2 p = ((const longlong2*)ei)[(E + e0) >> 1];
        d0 = (int)p.x; d1 = (int)p.y;
    } else {
        int2 p = ((const int2*)ei)[(E + e0) >> 1];
        d0 = p.x; d1 = p.y;
    }
    atomicAdd(&g_deg[d0], 1);
    if (e0 + 1 < E) atomicAdd(&g_deg[d1], 1);
}

// ---------------------------------------------------------------------------
// launch 1: decoupled-lookback exclusive scan; tail blocks transpose weights.
__global__ void __launch_bounds__(256)
k_scan(int n, int nb,
       const float* __restrict__ Wl, const float* __restrict__ Wr, int L)
{
    if ((int)blockIdx.x >= nb) {                  // weight transpose duty
        int idx = ((int)blockIdx.x - nb) * 256 + threadIdx.x;
        int tot = L * 2 * 4096;
        if (idx < tot) {
            int l  = idx >> 13;
            int r  = idx & 8191;
            int m  = r >> 12;
            int jk = r & 4095;
            int j  = jk >> 6;
            int k  = jk & 63;
            const float* W = m ? Wr : Wl;
            g_wT[(size_t)(l * 2 + m) * WT_MAT + k * WTP + j] =
                W[(size_t)l * 4096 + j * 64 + k];
        }
        return;
    }

    __shared__ int s[256];
    __shared__ int s_prefix;
    const int tid = threadIdx.x;
    const int b   = blockIdx.x;
    const int v   = b * 256 + tid;
    int d = (v < n) ? g_deg[v] : 0;

    s[tid] = d;
    __syncthreads();
    #pragma unroll
    for (int off = 1; off < 256; off <<= 1) {
        int t = (tid >= off) ? s[tid - off] : 0;
        __syncthreads();
        s[tid] += t;
        __syncthreads();
    }
    int total = s[255];

    if (tid == 0) {
        unsigned long long st = ((b == 0 ? FLG_INC : FLG_AGG) << 32) | (unsigned)total;
        atomicExch(&g_state[b], st);
        if (b == 0) s_prefix = 0;
    }

    if (b > 0 && tid < 32) {
        const int lane = tid;
        unsigned prefix = 0;
        int idx = b - 1;
        while (true) {
            int look = idx - lane;
            unsigned long long st = (look >= 0) ? atomicAdd(&g_state[look], 0ULL)
                                                : (FLG_INC << 32);
            unsigned flag = (unsigned)(st >> 32);
            unsigned val  = (unsigned)st;
            unsigned bEmpty = __ballot_sync(0xffffffffu, flag == 0u);
            unsigned bInc   = __ballot_sync(0xffffffffu, flag == (unsigned)FLG_INC);
            int firstInc   = bInc   ? (__ffs(bInc) - 1)   : 32;
            int firstEmpty = bEmpty ? (__ffs(bEmpty) - 1) : 32;
            if (firstEmpty < firstInc) continue;          // hole in window: spin
            int lim = firstInc < 31 ? firstInc : 31;
            unsigned c = (lane <= lim) ? val : 0;
            #pragma unroll
            for (int o = 16; o > 0; o >>= 1) c += __shfl_down_sync(0xffffffffu, c, o);
            c = __shfl_sync(0xffffffffu, c, 0);
            prefix += c;
            if (firstInc < 32) break;
            idx -= 32;
        }
        if (lane == 0) {
            atomicExch(&g_state[b], (FLG_INC << 32) | (unsigned)(prefix + total));
            s_prefix = (int)prefix;
        }
    }
    __syncthreads();

    if (v < n) {
        int r = s_prefix + s[tid] - d;
        g_row[v] = r;
        g_cur[v] = r;
        g_inv[v] = 1.0f / (float)max(d, 1);
    }
}

// ---------------------------------------------------------------------------
// launch 2: scatter src into CSR col, 2 edges/thread.
__global__ void __launch_bounds__(256) k_build(const void* __restrict__ ei, int E) {
    int t = blockIdx.x * blockDim.x + threadIdx.x;
    int e0 = t * 2;
    if (e0 >= E) return;
    int is64 = probe_is64((const int*)ei);
    int s0, s1, d0, d1;
    if (is64) {
        longlong2 sp = ((const longlong2*)ei)[e0 >> 1];
        longlong2 dp = ((const longlong2*)ei)[(E + e0) >> 1];
        s0 = (int)sp.x; s1 = (int)sp.y;
        d0 = (int)dp.x; d1 = (int)dp.y;
    } else {
        int2 sp = ((const int2*)ei)[e0 >> 1];
        int2 dp = ((const int2*)ei)[(E + e0) >> 1];
        s0 = sp.x; s1 = sp.y;
        d0 = dp.x; d1 = dp.y;
    }
    int p0 = atomicAdd(&g_cur[d0], 1);
    g_col[p0] = s0;
    if (e0 + 1 < E) {
        int p1 = atomicAdd(&g_cur[d1], 1);
        g_col[p1] = s1;
    }
}

// ---------------------------------------------------------------------------
// Gather: warp per node, lane owns cols [2*lane, 2*lane+1], 8 rows in flight.
__global__ void __launch_bounds__(256)
k_gather(const float* __restrict__ xin, int n)
{
    int gw   = (blockIdx.x * blockDim.x + threadIdx.x) >> 5;
    int lane = threadIdx.x & 31;
    if (gw >= n) return;
    const int v = gw;

    const float2* x2 = (const float2*)xin;
    float2 acc = make_float2(0.f, 0.f);

    int rs  = g_row[v];
    int end = rs + g_deg[v];
    int e = rs;
    for (; e + 8 <= end; e += 8) {
        int s0 = g_col[e+0], s1 = g_col[e+1], s2 = g_col[e+2], s3 = g_col[e+3];
        int s4 = g_col[e+4], s5 = g_col[e+5], s6 = g_col[e+6], s7 = g_col[e+7];
        float2 a0 = x2[(size_t)s0*32 + lane], a1 = x2[(size_t)s1*32 + lane];
        float2 a2 = x2[(size_t)s2*32 + lane], a3 = x2[(size_t)s3*32 + lane];
        float2 a4 = x2[(size_t)s4*32 + lane], a5 = x2[(size_t)s5*32 + lane];
        float2 a6 = x2[(size_t)s6*32 + lane], a7 = x2[(size_t)s7*32 + lane];
        acc.x += ((a0.x + a1.x) + (a2.x + a3.x)) + ((a4.x + a5.x) + (a6.x + a7.x));
        acc.y += ((a0.y + a1.y) + (a2.y + a3.y)) + ((a4.y + a5.y) + (a6.y + a7.y));
    }
    for (; e + 4 <= end; e += 4) {
        int s0 = g_col[e+0], s1 = g_col[e+1], s2 = g_col[e+2], s3 = g_col[e+3];
        float2 a0 = x2[(size_t)s0*32 + lane], a1 = x2[(size_t)s1*32 + lane];
        float2 a2 = x2[(size_t)s2*32 + lane], a3 = x2[(size_t)s3*32 + lane];
        acc.x += (a0.x + a1.x) + (a2.x + a3.x);
        acc.y += (a0.y + a1.y) + (a2.y + a3.y);
    }
    for (; e < end; ++e) {
        float2 a0 = x2[(size_t)g_col[e]*32 + lane];
        acc.x += a0.x; acc.y += a0.y;
    }
    float iv = g_inv[v];
    acc.x *= iv; acc.y *= iv;
    *(float2*)(g_agg + (size_t)v * 64 + lane * 2) = acc;
}

// ---------------------------------------------------------------------------
// GEMM: 128 nodes / 256 threads; thread = 4 nodes x 8 features, FFMA2.
// Warp layout: all lanes share jg -> weight LDS is broadcast; input LDS.64
// lane-stride = NPAD=66 words (bank 2) -> conflict-free half-warp phases.
__global__ void __launch_bounds__(256, 2)
k_gemm(const float* __restrict__ xin, const float* __restrict__ bl,
       float* __restrict__ xout, int n, int l)
{
    extern __shared__ float smem[];
    float* sWl = smem;                 // [k][j], stride WTP
    float* sWr = sWl + WT_MAT;
    float* sA  = sWr + WT_MAT;         // [node][k], stride NPAD
    float* sX  = sA  + 128 * NPAD;

    const int tid  = threadIdx.x;
    const int base = blockIdx.x * 128;

    // Stage weights: straight copy of 2*WT_MAT floats
    {
        const float4* wsrc = (const float4*)(g_wT + (size_t)l * 2 * WT_MAT);
        float4* wdst = (float4*)smem;
        #pragma unroll 1
        for (int idx = tid; idx < 2 * WT_MAT / 4; idx += 256)
            wdst[idx] = wsrc[idx];
    }
    // Stage agg + root rows (float2 stores: NPAD=66 is 8B-aligned only)
    for (int idx = tid; idx < 128 * 16; idx += 256) {
        int v = idx >> 4, c = idx & 15;
        int vg = base + v;
        float4 a  = make_float4(0.f, 0.f, 0.f, 0.f);
        float4 xv = a;
        if (vg < n) {
            a  = *(const float4*)(g_agg + (size_t)vg * 64 + c * 4);
            xv = *(const float4*)(xin   + (size_t)vg * 64 + c * 4);
        }
        *(float2*)(sA + v * NPAD + c * 4)     = make_float2(a.x, a.y);
        *(float2*)(sA + v * NPAD + c * 4 + 2) = make_float2(a.z, a.w);
        *(float2*)(sX + v * NPAD + c * 4)     = make_float2(xv.x, xv.y);
        *(float2*)(sX + v * NPAD + c * 4 + 2) = make_float2(xv.z, xv.w);
    }
    __syncthreads();

    const int ng = tid & 31;       // node lane: LDS stride 66 -> conflict-free
    const int jg = tid >> 5;       // 0..7, uniform per warp -> broadcast LDS
    const int j0 = jg * 8;

    unsigned long long acc2[4][4];
    #pragma unroll
    for (int i = 0; i < 4; ++i)
        #pragma unroll
        for (int p = 0; p < 4; ++p) acc2[i][p] = 0ull;

    #pragma unroll 2
    for (int k2 = 0; k2 < 32; ++k2) {
        int k0 = k2 * 2;
        ulonglong2 wl0a = *(const ulonglong2*)(sWl + (k0+0) * WTP + j0);
        ulonglong2 wl0b = *(const ulonglong2*)(sWl + (k0+0) * WTP + j0 + 4);
        ulonglong2 wl1a = *(const ulonglong2*)(sWl + (k0+1) * WTP + j0);
        ulonglong2 wl1b = *(const ulonglong2*)(sWl + (k0+1) * WTP + j0 + 4);
        ulonglong2 wr0a = *(const ulonglong2*)(sWr + (k0+0) * WTP + j0);
        ulonglong2 wr0b = *(const ulonglong2*)(sWr + (k0+0) * WTP + j0 + 4);
        ulonglong2 wr1a = *(const ulonglong2*)(sWr + (k0+1) * WTP + j0);
        ulonglong2 wr1b = *(const ulonglong2*)(sWr + (k0+1) * WTP + j0 + 4);

        #pragma unroll
        for (int i = 0; i < 4; ++i) {
            int v = i * 32 + ng;
            float2 a  = *(const float2*)(sA + v * NPAD + k0);
            float2 xv = *(const float2*)(sX + v * NPAD + k0);
            unsigned long long b;
            PACK2(b, a.x, a.x);
            FFMA2(acc2[i][0], wl0a.x, b); FFMA2(acc2[i][1], wl0a.y, b);
            FFMA2(acc2[i][2], wl0b.x, b); FFMA2(acc2[i][3], wl0b.y, b);
            PACK2(b, a.y, a.y);
            FFMA2(acc2[i][0], wl1a.x, b); FFMA2(acc2[i][1], wl1a.y, b);
            FFMA2(acc2[i][2], wl1b.x, b); FFMA2(acc2[i][3], wl1b.y, b);
            PACK2(b, xv.x, xv.x);
            FFMA2(acc2[i][0], wr0a.x, b); FFMA2(acc2[i][1], wr0a.y, b);
            FFMA2(acc2[i][2], wr0b.x, b); FFMA2(acc2[i][3], wr0b.y, b);
            PACK2(b, xv.y, xv.y);
            FFMA2(acc2[i][0], wr1a.x, b); FFMA2(acc2[i][1], wr1a.y, b);
            FFMA2(acc2[i][2], wr1b.x, b); FFMA2(acc2[i][3], wr1b.y, b);
        }
    }

    float4 bias0 = *(const float4*)(bl + j0);
    float4 bias1 = *(const float4*)(bl + j0 + 4);

    #pragma unroll
    for (int i = 0; i < 4; ++i) {
        int vg = base + i * 32 + ng;
        if (vg < n) {
            float4 o0, o1;
            float lo, hi;
            UNPACK2(lo, hi, acc2[i][0]); o0.x = lo; o0.y = hi;
            UNPACK2(lo, hi, acc2[i][1]); o0.z = lo; o0.w = hi;
            UNPACK2(lo, hi, acc2[i][2]); o1.x = lo; o1.y = hi;
            UNPACK2(lo, hi, acc2[i][3]); o1.z = lo; o1.w = hi;
            o0.x = fmaxf(o0.x + bias0.x, 0.f);
            o0.y = fmaxf(o0.y + bias0.y, 0.f);
            o0.z = fmaxf(o0.z + bias0.z, 0.f);
            o0.w = fmaxf(o0.w + bias0.w, 0.f);
            o1.x = fmaxf(o1.x + bias1.x, 0.f);
            o1.y = fmaxf(o1.y + bias1.y, 0.f);
            o1.z = fmaxf(o1.z + bias1.z, 0.f);
            o1.w = fmaxf(o1.w + bias1.w, 0.f);
            *(float4*)(xout + (size_t)vg * 64 + j0)     = o0;
            *(float4*)(xout + (size_t)vg * 64 + j0 + 4) = o1;
        }
    }
}

// ---------------------------------------------------------------------------
extern "C" void kernel_launch(void* const* d_in, const int* in_sizes, int n_in,
                              void* d_out, int out_size)
{
    const float* x  = (const float*)d_in[0];
    const float* Wl = (const float*)d_in[1];
    const float* bl = (const float*)d_in[2];
    const float* Wr = (const float*)d_in[3];
    const void*  ei = d_in[4];

    const int n = in_sizes[0] / DD;
    const int E = in_sizes[4] / 2;
    const int L = in_sizes[1] / (DD * DD);

    float *bufA = nullptr, *bufB = nullptr;
    void* degp = nullptr;
    cudaGetSymbolAddress((void**)&bufA, g_bufA);
    cudaGetSymbolAddress((void**)&bufB, g_bufB);
    cudaGetSymbolAddress(&degp, g_deg);

    cudaFuncSetAttribute(k_gemm, cudaFuncAttributeMaxDynamicSharedMemorySize,
                         GEMM_SMEM);

    const int nb  = (n + 255) / 256;                // 391 <= 512
    const int wb  = (L * 2 * 4096 + 255) / 256;     // 96 transpose blocks
    const int eb2 = (E / 2 + 255) / 256;            // 2 edges per thread

    cudaMemsetAsync(degp, 0, (size_t)n * sizeof(int));
    k_deg<<<eb2, 256>>>(ei, E);                      // launch 0
    k_scan<<<nb + wb, 256>>>(n, nb, Wl, Wr, L);      // launch 1
    k_build<<<eb2, 256>>>(ei, E);                    // launch 2

    const float* cur = x;
    for (int l = 0; l < L; ++l) {
        float* outp = (l == L - 1) ? (float*)d_out
                                   : ((l & 1) ? bufB : bufA);
        int gblocks = (n * 32 + 255) / 256;
        k_gather<<<gblocks, 256>>>(cur, n);          // launch 3 (l=0): profiled
        k_gemm<<<(n + 127) / 128, 256, GEMM_SMEM>>>(
            cur, bl + (size_t)l * DD, outp, n, l);
        cur = outp;
    }
}